// round 4
// baseline (speedup 1.0000x reference)
#include <cuda_runtime.h>
#include <cuda_bf16.h>
#include <math.h>

// Problem constants (fixed by the reference)
#define DM   2048      // d_model
#define HN   16        // heads
#define DK   128       // head dim
#define BB   4         // batch
#define SL   2048      // seq len
#define MTOT (BB*SL)   // 8192 total rows

// ---------------------------------------------------------------------------
// Scratch (device globals: no allocation allowed)
// q,k,v in [B,H,S,DK] layout; ctx in [B,S,DM] layout
// ---------------------------------------------------------------------------
__device__ float g_q[(size_t)BB*HN*SL*DK];
__device__ float g_k[(size_t)BB*HN*SL*DK];
__device__ float g_v[(size_t)BB*HN*SL*DK];
__device__ float g_ctx[(size_t)BB*SL*DM];

// ---------------------------------------------------------------------------
// NT GEMM: C[m,n] = sum_k A[m,k] * W[n,k]
// A: [MTOT, DM] row-major, W: [DM, DM] row-major (so C = A @ W^T)
// reshape=1: write C into head layout [(b*HN+h)*SL + s]*DK + d  (n = h*128+d)
// reshape=0: write C row-major [m*DM + n]
// Tile: 128x128x16, 256 threads, 8x8 per thread.
// ---------------------------------------------------------------------------
__global__ void __launch_bounds__(256) gemm_nt_kernel(
    const float* __restrict__ A,
    const float* __restrict__ W,
    float* __restrict__ C,
    int reshape)
{
    __shared__ float As[16][132];
    __shared__ float Bs[16][132];

    const int t  = threadIdx.x;
    const int m0 = blockIdx.y * 128;
    const int n0 = blockIdx.x * 128;
    const int tx = t & 15;
    const int ty = t >> 4;

    float acc[8][8];
#pragma unroll
    for (int i = 0; i < 8; i++)
#pragma unroll
        for (int j = 0; j < 8; j++) acc[i][j] = 0.f;

    for (int k0 = 0; k0 < DM; k0 += 16) {
        // Load 128x16 tiles of A and W, transposed into smem (K-major rows)
#pragma unroll
        for (int l = 0; l < 2; l++) {
            int id  = t + l * 256;          // 0..511
            int row = id >> 2;              // 0..127
            int kc  = id & 3;               // float4 index within 16 cols
            float4 va = *reinterpret_cast<const float4*>(
                &A[(size_t)(m0 + row) * DM + k0 + kc * 4]);
            As[kc*4+0][row] = va.x; As[kc*4+1][row] = va.y;
            As[kc*4+2][row] = va.z; As[kc*4+3][row] = va.w;
            float4 vb = *reinterpret_cast<const float4*>(
                &W[(size_t)(n0 + row) * DM + k0 + kc * 4]);
            Bs[kc*4+0][row] = vb.x; Bs[kc*4+1][row] = vb.y;
            Bs[kc*4+2][row] = vb.z; Bs[kc*4+3][row] = vb.w;
        }
        __syncthreads();

#pragma unroll
        for (int kk = 0; kk < 16; kk++) {
            float a[8], b[8];
            *reinterpret_cast<float4*>(&a[0]) = *reinterpret_cast<float4*>(&As[kk][ty*8]);
            *reinterpret_cast<float4*>(&a[4]) = *reinterpret_cast<float4*>(&As[kk][ty*8+4]);
            *reinterpret_cast<float4*>(&b[0]) = *reinterpret_cast<float4*>(&Bs[kk][tx*8]);
            *reinterpret_cast<float4*>(&b[4]) = *reinterpret_cast<float4*>(&Bs[kk][tx*8+4]);
#pragma unroll
            for (int i = 0; i < 8; i++)
#pragma unroll
                for (int j = 0; j < 8; j++)
                    acc[i][j] = fmaf(a[i], b[j], acc[i][j]);
        }
        __syncthreads();
    }

    // Epilogue
#pragma unroll
    for (int i = 0; i < 8; i++) {
        int m = m0 + ty * 8 + i;
        int b = m >> 11;            // m / SL
        int s = m & (SL - 1);
#pragma unroll
        for (int j = 0; j < 8; j++) {
            int n = n0 + tx * 8 + j;
            if (reshape) {
                int h = n >> 7;     // n / DK
                int d = n & (DK - 1);
                C[((size_t)(b * HN + h) * SL + s) * DK + d] = acc[i][j];
            } else {
                C[(size_t)m * DM + n] = acc[i][j];
            }
        }
    }
}

// ---------------------------------------------------------------------------
// Flash-style causal attention, fp32.
// grid = (S/64, B*H), 256 threads.
// Per block: 64 query rows; iterate over 64-row K/V tiles with online softmax.
// Dynamic smem: Qs/Ks/Vs [64][132] + Ss [64][68]  = 118784 bytes.
// ---------------------------------------------------------------------------
#define BQ  64
#define BKV 64
#define ATTN_SMEM_BYTES ((3*64*132 + 64*68) * 4)

__global__ void __launch_bounds__(256) attn_kernel(
    const float* __restrict__ qg,
    const float* __restrict__ kg,
    const float* __restrict__ vg,
    float* __restrict__ ctx,
    const int* __restrict__ use_mask_p)
{
    extern __shared__ float sm[];
    float* Qs = sm;                    // 64*132
    float* Ks = Qs + 64 * 132;         // 64*132
    float* Vs = Ks + 64 * 132;         // 64*132
    float* Ss = Vs + 64 * 132;         // 64*68

    const int t  = threadIdx.x;
    const int qb = blockIdx.x;
    const int bh = blockIdx.y;
    const int q0 = qb * BQ;

    const float* qbase = qg + (size_t)bh * SL * DK;
    const float* kbase = kg + (size_t)bh * SL * DK;
    const float* vbase = vg + (size_t)bh * SL * DK;

    const int use_mask = *use_mask_p;
    const int nkv = use_mask ? (qb + 1) : (SL / BKV);

    // Load Q tile
    for (int id = t; id < BQ * 32; id += 256) {
        int row = id >> 5;
        int dc  = id & 31;
        *reinterpret_cast<float4*>(&Qs[row * 132 + dc * 4]) =
            *reinterpret_cast<const float4*>(&qbase[(size_t)(q0 + row) * DK + dc * 4]);
    }

    const int tx   = t & 15;   // score-phase col group
    const int ty   = t >> 4;   // score-phase row group
    const int rowp = t >> 2;   // softmax/PV row (0..63)
    const int dq   = t & 3;    // softmax/PV d-quadrant (32 d's each)

    float m_i = -1e30f, l_i = 0.f;
    float acc[32];
#pragma unroll
    for (int i = 0; i < 32; i++) acc[i] = 0.f;

    const float scale = 0.08838834764831845f;   // 1/sqrt(128)

    for (int kvb = 0; kvb < nkv; kvb++) {
        const int j0 = kvb * BKV;
        __syncthreads();   // previous iteration's Ss/Vs consumers done

        for (int id = t; id < BKV * 32; id += 256) {
            int row = id >> 5;
            int dc  = id & 31;
            *reinterpret_cast<float4*>(&Ks[row * 132 + dc * 4]) =
                *reinterpret_cast<const float4*>(&kbase[(size_t)(j0 + row) * DK + dc * 4]);
            *reinterpret_cast<float4*>(&Vs[row * 132 + dc * 4]) =
                *reinterpret_cast<const float4*>(&vbase[(size_t)(j0 + row) * DK + dc * 4]);
        }
        __syncthreads();

        // --- scores: 4x4 per thread over 64x64 tile ---
        float sc[4][4];
#pragma unroll
        for (int i = 0; i < 4; i++)
#pragma unroll
            for (int j = 0; j < 4; j++) sc[i][j] = 0.f;

        for (int d = 0; d < DK; d += 4) {
            float4 qv[4], kv[4];
#pragma unroll
            for (int i = 0; i < 4; i++)
                qv[i] = *reinterpret_cast<float4*>(&Qs[(ty * 4 + i) * 132 + d]);
#pragma unroll
            for (int j = 0; j < 4; j++)
                kv[j] = *reinterpret_cast<float4*>(&Ks[(tx * 4 + j) * 132 + d]);
#pragma unroll
            for (int i = 0; i < 4; i++)
#pragma unroll
                for (int j = 0; j < 4; j++) {
                    sc[i][j] = fmaf(qv[i].x, kv[j].x, sc[i][j]);
                    sc[i][j] = fmaf(qv[i].y, kv[j].y, sc[i][j]);
                    sc[i][j] = fmaf(qv[i].z, kv[j].z, sc[i][j]);
                    sc[i][j] = fmaf(qv[i].w, kv[j].w, sc[i][j]);
                }
        }

#pragma unroll
        for (int i = 0; i < 4; i++) {
            int gr = q0 + ty * 4 + i;
#pragma unroll
            for (int j = 0; j < 4; j++) {
                int gc = j0 + tx * 4 + j;
                float val = sc[i][j] * scale;
                if (use_mask && gc > gr) val = -1e30f;
                Ss[(ty * 4 + i) * 68 + tx * 4 + j] = val;
            }
        }
        __syncthreads();

        // --- online softmax update (4 threads per row, same warp) ---
        float sv[16];
        float tmax = -1e30f;
#pragma unroll
        for (int j = 0; j < 16; j++) {
            sv[j] = Ss[rowp * 68 + dq * 16 + j];
            tmax  = fmaxf(tmax, sv[j]);
        }
        tmax = fmaxf(tmax, __shfl_xor_sync(0xffffffffu, tmax, 1));
        tmax = fmaxf(tmax, __shfl_xor_sync(0xffffffffu, tmax, 2));

        float m_new = fmaxf(m_i, tmax);
        float alpha = __expf(m_i - m_new);
        float lsum  = 0.f;
#pragma unroll
        for (int j = 0; j < 16; j++) {
            sv[j] = __expf(sv[j] - m_new);
            lsum += sv[j];
        }
        lsum += __shfl_xor_sync(0xffffffffu, lsum, 1);
        lsum += __shfl_xor_sync(0xffffffffu, lsum, 2);

        l_i = l_i * alpha + lsum;
        m_i = m_new;
#pragma unroll
        for (int i = 0; i < 32; i++) acc[i] *= alpha;

        // write probs back (each row served by its own 4 same-warp threads)
#pragma unroll
        for (int j = 0; j < 16; j++) Ss[rowp * 68 + dq * 16 + j] = sv[j];
        __syncwarp();

        // --- PV: acc[d] += sum_j p[row][j] * V[j][d], d in dq*32..dq*32+31 ---
        for (int j = 0; j < BKV; j++) {
            float p = Ss[rowp * 68 + j];
#pragma unroll
            for (int c = 0; c < 8; c++) {
                float4 vv = *reinterpret_cast<float4*>(&Vs[j * 132 + dq * 32 + c * 4]);
                acc[c * 4 + 0] = fmaf(p, vv.x, acc[c * 4 + 0]);
                acc[c * 4 + 1] = fmaf(p, vv.y, acc[c * 4 + 1]);
                acc[c * 4 + 2] = fmaf(p, vv.z, acc[c * 4 + 2]);
                acc[c * 4 + 3] = fmaf(p, vv.w, acc[c * 4 + 3]);
            }
        }
    }

    // Epilogue: ctx[b][s][h*DK + d]
    const int b = bh >> 4;
    const int h = bh & 15;
    const int s_row = q0 + rowp;
    const float inv_l = 1.0f / l_i;
    const size_t base = ((size_t)(b * SL + s_row) * DM) + (size_t)h * DK + dq * 32;
#pragma unroll
    for (int c = 0; c < 8; c++) {
        float4 o;
        o.x = acc[c * 4 + 0] * inv_l;
        o.y = acc[c * 4 + 1] * inv_l;
        o.z = acc[c * 4 + 2] * inv_l;
        o.w = acc[c * 4 + 3] * inv_l;
        *reinterpret_cast<float4*>(&ctx[base + c * 4]) = o;
    }
}

// ---------------------------------------------------------------------------
// Launch
// Inputs (metadata order): x, Wq, Wk, Wv, Wo, use_mask
// ---------------------------------------------------------------------------
extern "C" void kernel_launch(void* const* d_in, const int* in_sizes, int n_in,
                              void* d_out, int out_size)
{
    const float* x   = (const float*)d_in[0];
    const float* Wq  = (const float*)d_in[1];
    const float* Wk  = (const float*)d_in[2];
    const float* Wv  = (const float*)d_in[3];
    const float* Wo  = (const float*)d_in[4];
    const int*   umk = (const int*)d_in[5];
    float*       out = (float*)d_out;

    float *qp, *kp, *vp, *cp;
    cudaGetSymbolAddress((void**)&qp, g_q);
    cudaGetSymbolAddress((void**)&kp, g_k);
    cudaGetSymbolAddress((void**)&vp, g_v);
    cudaGetSymbolAddress((void**)&cp, g_ctx);

    cudaFuncSetAttribute(attn_kernel,
                         cudaFuncAttributeMaxDynamicSharedMemorySize,
                         ATTN_SMEM_BYTES);

    dim3 ggrid(DM / 128, MTOT / 128);   // (16, 64)
    gemm_nt_kernel<<<ggrid, 256>>>(x, Wq, qp, 1);
    gemm_nt_kernel<<<ggrid, 256>>>(x, Wk, kp, 1);
    gemm_nt_kernel<<<ggrid, 256>>>(x, Wv, vp, 1);

    dim3 agrid(SL / BQ, BB * HN);       // (32, 64)
    attn_kernel<<<agrid, 256, ATTN_SMEM_BYTES>>>(qp, kp, vp, cp, umk);

    gemm_nt_kernel<<<ggrid, 256>>>(cp, Wo, out, 0);
}

// round 11
// speedup vs baseline: 1.2656x; 1.2656x over previous
#include <cuda_runtime.h>
#include <cuda_bf16.h>
#include <math.h>
#include <stdint.h>

// Problem constants (fixed by the reference)
#define DM   2048      // d_model
#define HN   16        // heads
#define DK   128       // head dim
#define BB   4         // batch
#define SL   2048      // seq len
#define MTOT (BB*SL)   // 8192 total rows

// ---------------------------------------------------------------------------
// Scratch (device globals: no allocation allowed)
// ---------------------------------------------------------------------------
__device__ float g_q[(size_t)BB*HN*SL*DK];
__device__ float g_k[(size_t)BB*HN*SL*DK];
__device__ float g_v[(size_t)BB*HN*SL*DK];
__device__ float g_ctx[(size_t)BB*SL*DM];

// bf16 hi/lo splits for tensor-core GEMMs
__device__ __nv_bfloat16 g_xh[(size_t)MTOT*DM];
__device__ __nv_bfloat16 g_xl[(size_t)MTOT*DM];
__device__ __nv_bfloat16 g_wh[(size_t)4*DM*DM];
__device__ __nv_bfloat16 g_wl[(size_t)4*DM*DM];
__device__ __nv_bfloat16 g_ch[(size_t)MTOT*DM];
__device__ __nv_bfloat16 g_cl[(size_t)MTOT*DM];

// ---------------------------------------------------------------------------
// Baseline-PTX helpers (NO 'a'-suffix features: this toolchain lowers through
// compute_103, so tcgen05/TMEM are unavailable. mma.sync/ldmatrix/cp.async
// are baseline sm_80+.)
// ---------------------------------------------------------------------------
__device__ __forceinline__ uint32_t smem_u32(const void* p) {
    uint32_t a;
    asm("{ .reg .u64 t; cvta.to.shared.u64 t, %1; cvt.u32.u64 %0, t; }"
        : "=r"(a) : "l"(p));
    return a;
}
__device__ __forceinline__ void cp_async16(uint32_t saddr, const void* gaddr) {
    asm volatile("cp.async.cg.shared.global [%0], [%1], 16;"
                 :: "r"(saddr), "l"(gaddr) : "memory");
}
#define CP_COMMIT() asm volatile("cp.async.commit_group;" ::: "memory")
#define CP_WAIT(n)  asm volatile("cp.async.wait_group %0;" :: "n"(n) : "memory")

__device__ __forceinline__ void ldsm4(uint32_t* r, uint32_t addr) {
    asm volatile("ldmatrix.sync.aligned.m8n8.x4.shared.b16 {%0,%1,%2,%3}, [%4];"
                 : "=r"(r[0]), "=r"(r[1]), "=r"(r[2]), "=r"(r[3]) : "r"(addr));
}
__device__ __forceinline__ void mma16816(float* c, const uint32_t* a, const uint32_t* b) {
    asm volatile(
        "mma.sync.aligned.m16n8k16.row.col.f32.bf16.bf16.f32 "
        "{%0,%1,%2,%3}, {%4,%5,%6,%7}, {%8,%9}, {%0,%1,%2,%3};"
        : "+f"(c[0]), "+f"(c[1]), "+f"(c[2]), "+f"(c[3])
        : "r"(a[0]), "r"(a[1]), "r"(a[2]), "r"(a[3]), "r"(b[0]), "r"(b[1]));
}

// ---------------------------------------------------------------------------
// fp32 -> bf16 hi/lo split (vectorized by 4)
// ---------------------------------------------------------------------------
__global__ void __launch_bounds__(256) split_kernel(
    const float* __restrict__ in,
    __nv_bfloat16* __restrict__ hi,
    __nv_bfloat16* __restrict__ lo,
    int n4)
{
    int i = blockIdx.x * blockDim.x + threadIdx.x;
    if (i >= n4) return;
    float4 v = reinterpret_cast<const float4*>(in)[i];
    __nv_bfloat16 h0 = __float2bfloat16(v.x);
    __nv_bfloat16 h1 = __float2bfloat16(v.y);
    __nv_bfloat16 h2 = __float2bfloat16(v.z);
    __nv_bfloat16 h3 = __float2bfloat16(v.w);
    __nv_bfloat16 l0 = __float2bfloat16(v.x - __bfloat162float(h0));
    __nv_bfloat16 l1 = __float2bfloat16(v.y - __bfloat162float(h1));
    __nv_bfloat16 l2 = __float2bfloat16(v.z - __bfloat162float(h2));
    __nv_bfloat16 l3 = __float2bfloat16(v.w - __bfloat162float(h3));
    reinterpret_cast<__nv_bfloat162*>(hi)[2*i+0] = __halves2bfloat162(h0, h1);
    reinterpret_cast<__nv_bfloat162*>(hi)[2*i+1] = __halves2bfloat162(h2, h3);
    reinterpret_cast<__nv_bfloat162*>(lo)[2*i+0] = __halves2bfloat162(l0, l1);
    reinterpret_cast<__nv_bfloat162*>(lo)[2*i+1] = __halves2bfloat162(l2, l3);
}

// ---------------------------------------------------------------------------
// HMMA GEMM: C[m,n] = sum_k A[m,k]*W[n,k], A=Ah+Al, W=Wh+Wl (bf16),
// C ~= Ah*Wh^T + Ah*Wl^T + Al*Wh^T (fp32 accum; drops only lo*lo ~2^-18).
// CTA tile 128x128, K-chunk 32, 2-stage cp.async pipeline, 256 threads.
// Warp grid 2(m) x 4(n); warp tile 64x32 = 4x4 m16n8k16 atoms.
// smem tiles padded to 40 bf16/row (80B) -> conflict-free ldmatrix.
// reshape=1: write head layout [(b*HN+h)*SL+s]*DK + d with h = blockIdx.x
// ---------------------------------------------------------------------------
#define GKC      32                       // K per chunk
#define NCH      (DM / GKC)               // 64 chunks
#define LDT      40                       // smem row stride in bf16 elems
#define TILE_B   (128 * LDT * 2)          // 10240 B per operand tile
#define OFF_AH   (0 * TILE_B)
#define OFF_AL   (1 * TILE_B)
#define OFF_BH   (2 * TILE_B)
#define OFF_BL   (3 * TILE_B)
#define STAGE_B  (4 * TILE_B)             // 40960 B
#define GEMM_SMEM (2 * STAGE_B)           // 81920 B

__global__ void __launch_bounds__(256, 1) gemm_tc_kernel(
    const __nv_bfloat16* __restrict__ Ah,
    const __nv_bfloat16* __restrict__ Al,
    const __nv_bfloat16* __restrict__ Bh,
    const __nv_bfloat16* __restrict__ Bl,
    float* __restrict__ C,
    int reshape)
{
    extern __shared__ char smem[];
    const uint32_t smem_base = smem_u32(smem);
    const int t   = threadIdx.x;
    const int wid = t >> 5;
    const int lid = t & 31;
    const int n0  = blockIdx.x * 128;
    const int m0  = blockIdx.y * 128;
    const int wm  = (wid >> 2) * 64;      // warp m offset (0 or 64)
    const int wn  = (wid & 3) * 32;       // warp n offset (0,32,64,96)

    // global-load geometry: id -> (row 0..127, 16B chunk 0..3), 2 ids/thread/tile
    const int row0 = t >> 2,  ch0 = t & 3;
    const int row1 = (t + 256) >> 2, ch1 = (t + 256) & 3;

    // ldmatrix per-lane byte offsets within a tile (k16-step adds 32B)
    uint32_t aoff[4], boff[2];
#pragma unroll
    for (int i = 0; i < 4; i++)
        aoff[i] = (uint32_t)(((wm + i * 16 + (lid & 15)) * LDT + ((lid >> 4) * 8)) * 2);
#pragma unroll
    for (int p = 0; p < 2; p++)
        boff[p] = (uint32_t)(((wn + p * 16 + (lid & 7) + ((lid >> 4) * 8)) * LDT
                              + (((lid >> 3) & 1) * 8)) * 2);

    float acc[4][4][4];
#pragma unroll
    for (int i = 0; i < 4; i++)
#pragma unroll
        for (int j = 0; j < 4; j++)
#pragma unroll
            for (int r = 0; r < 4; r++) acc[i][j][r] = 0.f;

    // stage loader
    auto load_stage = [&](int it, int s) {
        const uint32_t sb = smem_base + s * STAGE_B;
        const size_t k0 = (size_t)it * GKC;
#pragma unroll
        for (int p = 0; p < 2; p++) {
            const int row = p ? row1 : row0;
            const int ch  = p ? ch1  : ch0;
            const uint32_t so = (uint32_t)((row * LDT + ch * 8) * 2);
            const size_t ga = (size_t)(m0 + row) * DM + k0 + ch * 8;
            const size_t gb = (size_t)(n0 + row) * DM + k0 + ch * 8;
            cp_async16(sb + OFF_AH + so, Ah + ga);
            cp_async16(sb + OFF_AL + so, Al + ga);
            cp_async16(sb + OFF_BH + so, Bh + gb);
            cp_async16(sb + OFF_BL + so, Bl + gb);
        }
        CP_COMMIT();
    };

    load_stage(0, 0);

    for (int it = 0; it < NCH; ++it) {
        const int s = it & 1;
        if (it + 1 < NCH) { load_stage(it + 1, s ^ 1); CP_WAIT(1); }
        else             { CP_WAIT(0); }
        __syncthreads();

        const uint32_t sb = smem_base + s * STAGE_B;
#pragma unroll
        for (int ks = 0; ks < 2; ks++) {
            const uint32_t kb = ks * 32;   // 16 elems * 2B
            uint32_t ah[4][4], al[4][4], bh[2][4], bl[2][4];
#pragma unroll
            for (int i = 0; i < 4; i++) {
                ldsm4(ah[i], sb + OFF_AH + aoff[i] + kb);
                ldsm4(al[i], sb + OFF_AL + aoff[i] + kb);
            }
#pragma unroll
            for (int p = 0; p < 2; p++) {
                ldsm4(bh[p], sb + OFF_BH + boff[p] + kb);
                ldsm4(bl[p], sb + OFF_BL + boff[p] + kb);
            }
#pragma unroll
            for (int i = 0; i < 4; i++) {
#pragma unroll
                for (int j = 0; j < 4; j++) {
                    const int p  = j >> 1;
                    const int jj = (j & 1) * 2;
                    uint32_t bhp[2] = { bh[p][jj], bh[p][jj + 1] };
                    uint32_t blp[2] = { bl[p][jj], bl[p][jj + 1] };
                    mma16816(acc[i][j], ah[i], bhp);
                    mma16816(acc[i][j], ah[i], blp);
                    mma16816(acc[i][j], al[i], bhp);
                }
            }
        }
        __syncthreads();
    }

    // epilogue: lane l holds (m = q/4 [+8], n = 2*(q%4) [+1]) per atom
    const int lr = lid >> 2;          // 0..7
    const int lc = (lid & 3) * 2;     // 0,2,4,6
#pragma unroll
    for (int i = 0; i < 4; i++) {
#pragma unroll
        for (int half = 0; half < 2; half++) {
            const int ml = wm + i * 16 + lr + half * 8;
            const int m  = m0 + ml;
            const int b  = m >> 11;
            const int srow = m & (SL - 1);
            float* dst;
            if (reshape) {
                dst = C + ((size_t)(b * HN + blockIdx.x) * SL + srow) * DK;
            } else {
                dst = C + (size_t)m * DM + n0;
            }
#pragma unroll
            for (int j = 0; j < 4; j++) {
                const int nl = wn + j * 8 + lc;
                float2 o;
                o.x = acc[i][j][half * 2 + 0];
                o.y = acc[i][j][half * 2 + 1];
                *reinterpret_cast<float2*>(dst + nl) = o;
            }
        }
    }
}

// ---------------------------------------------------------------------------
// Flash-style causal attention, fp32 (unchanged from passing baseline)
// ---------------------------------------------------------------------------
#define BQ  64
#define BKV 64
#define ATTN_SMEM_BYTES ((3*64*132 + 64*68) * 4)

__global__ void __launch_bounds__(256) attn_kernel(
    const float* __restrict__ qg,
    const float* __restrict__ kg,
    const float* __restrict__ vg,
    float* __restrict__ ctx,
    const int* __restrict__ use_mask_p)
{
    extern __shared__ float sm[];
    float* Qs = sm;                    // 64*132
    float* Ks = Qs + 64 * 132;         // 64*132
    float* Vs = Ks + 64 * 132;         // 64*132
    float* Ss = Vs + 64 * 132;         // 64*68

    const int t  = threadIdx.x;
    const int qb = blockIdx.x;
    const int bh = blockIdx.y;
    const int q0 = qb * BQ;

    const float* qbase = qg + (size_t)bh * SL * DK;
    const float* kbase = kg + (size_t)bh * SL * DK;
    const float* vbase = vg + (size_t)bh * SL * DK;

    const int use_mask = *use_mask_p;
    const int nkv = use_mask ? (qb + 1) : (SL / BKV);

    for (int id = t; id < BQ * 32; id += 256) {
        int row = id >> 5;
        int dc  = id & 31;
        *reinterpret_cast<float4*>(&Qs[row * 132 + dc * 4]) =
            *reinterpret_cast<const float4*>(&qbase[(size_t)(q0 + row) * DK + dc * 4]);
    }

    const int tx   = t & 15;
    const int ty   = t >> 4;
    const int rowp = t >> 2;
    const int dq   = t & 3;

    float m_i = -1e30f, l_i = 0.f;
    float acc[32];
#pragma unroll
    for (int i = 0; i < 32; i++) acc[i] = 0.f;

    const float scale = 0.08838834764831845f;   // 1/sqrt(128)

    for (int kvb = 0; kvb < nkv; kvb++) {
        const int j0 = kvb * BKV;
        __syncthreads();

        for (int id = t; id < BKV * 32; id += 256) {
            int row = id >> 5;
            int dc  = id & 31;
            *reinterpret_cast<float4*>(&Ks[row * 132 + dc * 4]) =
                *reinterpret_cast<const float4*>(&kbase[(size_t)(j0 + row) * DK + dc * 4]);
            *reinterpret_cast<float4*>(&Vs[row * 132 + dc * 4]) =
                *reinterpret_cast<const float4*>(&vbase[(size_t)(j0 + row) * DK + dc * 4]);
        }
        __syncthreads();

        float sc[4][4];
#pragma unroll
        for (int i = 0; i < 4; i++)
#pragma unroll
            for (int j = 0; j < 4; j++) sc[i][j] = 0.f;

        for (int d = 0; d < DK; d += 4) {
            float4 qv[4], kv[4];
#pragma unroll
            for (int i = 0; i < 4; i++)
                qv[i] = *reinterpret_cast<float4*>(&Qs[(ty * 4 + i) * 132 + d]);
#pragma unroll
            for (int j = 0; j < 4; j++)
                kv[j] = *reinterpret_cast<float4*>(&Ks[(tx * 4 + j) * 132 + d]);
#pragma unroll
            for (int i = 0; i < 4; i++)
#pragma unroll
                for (int j = 0; j < 4; j++) {
                    sc[i][j] = fmaf(qv[i].x, kv[j].x, sc[i][j]);
                    sc[i][j] = fmaf(qv[i].y, kv[j].y, sc[i][j]);
                    sc[i][j] = fmaf(qv[i].z, kv[j].z, sc[i][j]);
                    sc[i][j] = fmaf(qv[i].w, kv[j].w, sc[i][j]);
                }
        }

#pragma unroll
        for (int i = 0; i < 4; i++) {
            int gr = q0 + ty * 4 + i;
#pragma unroll
            for (int j = 0; j < 4; j++) {
                int gc = j0 + tx * 4 + j;
                float val = sc[i][j] * scale;
                if (use_mask && gc > gr) val = -1e30f;
                Ss[(ty * 4 + i) * 68 + tx * 4 + j] = val;
            }
        }
        __syncthreads();

        float sv[16];
        float tmax = -1e30f;
#pragma unroll
        for (int j = 0; j < 16; j++) {
            sv[j] = Ss[rowp * 68 + dq * 16 + j];
            tmax  = fmaxf(tmax, sv[j]);
        }
        tmax = fmaxf(tmax, __shfl_xor_sync(0xffffffffu, tmax, 1));
        tmax = fmaxf(tmax, __shfl_xor_sync(0xffffffffu, tmax, 2));

        float m_new = fmaxf(m_i, tmax);
        float alpha = __expf(m_i - m_new);
        float lsum  = 0.f;
#pragma unroll
        for (int j = 0; j < 16; j++) {
            sv[j] = __expf(sv[j] - m_new);
            lsum += sv[j];
        }
        lsum += __shfl_xor_sync(0xffffffffu, lsum, 1);
        lsum += __shfl_xor_sync(0xffffffffu, lsum, 2);

        l_i = l_i * alpha + lsum;
        m_i = m_new;
#pragma unroll
        for (int i = 0; i < 32; i++) acc[i] *= alpha;

#pragma unroll
        for (int j = 0; j < 16; j++) Ss[rowp * 68 + dq * 16 + j] = sv[j];
        __syncwarp();

        for (int j = 0; j < BKV; j++) {
            float p = Ss[rowp * 68 + j];
#pragma unroll
            for (int c = 0; c < 8; c++) {
                float4 vv = *reinterpret_cast<float4*>(&Vs[j * 132 + dq * 32 + c * 4]);
                acc[c * 4 + 0] = fmaf(p, vv.x, acc[c * 4 + 0]);
                acc[c * 4 + 1] = fmaf(p, vv.y, acc[c * 4 + 1]);
                acc[c * 4 + 2] = fmaf(p, vv.z, acc[c * 4 + 2]);
                acc[c * 4 + 3] = fmaf(p, vv.w, acc[c * 4 + 3]);
            }
        }
    }

    const int b = bh >> 4;
    const int h = bh & 15;
    const int s_row = q0 + rowp;
    const float inv_l = 1.0f / l_i;
    const size_t base = ((size_t)(b * SL + s_row) * DM) + (size_t)h * DK + dq * 32;
#pragma unroll
    for (int c = 0; c < 8; c++) {
        float4 o;
        o.x = acc[c * 4 + 0] * inv_l;
        o.y = acc[c * 4 + 1] * inv_l;
        o.z = acc[c * 4 + 2] * inv_l;
        o.w = acc[c * 4 + 3] * inv_l;
        *reinterpret_cast<float4*>(&ctx[base + c * 4]) = o;
    }
}

// ---------------------------------------------------------------------------
// Launch: x, Wq, Wk, Wv, Wo, use_mask
// ---------------------------------------------------------------------------
extern "C" void kernel_launch(void* const* d_in, const int* in_sizes, int n_in,
                              void* d_out, int out_size)
{
    const float* x   = (const float*)d_in[0];
    const float* Wq  = (const float*)d_in[1];
    const float* Wk  = (const float*)d_in[2];
    const float* Wv  = (const float*)d_in[3];
    const float* Wo  = (const float*)d_in[4];
    const int*   umk = (const int*)d_in[5];
    float*       out = (float*)d_out;

    float *qp, *kp, *vp, *cp;
    __nv_bfloat16 *xh, *xl, *wh, *wl, *ch, *cl;
    cudaGetSymbolAddress((void**)&qp, g_q);
    cudaGetSymbolAddress((void**)&kp, g_k);
    cudaGetSymbolAddress((void**)&vp, g_v);
    cudaGetSymbolAddress((void**)&cp, g_ctx);
    cudaGetSymbolAddress((void**)&xh, g_xh);
    cudaGetSymbolAddress((void**)&xl, g_xl);
    cudaGetSymbolAddress((void**)&wh, g_wh);
    cudaGetSymbolAddress((void**)&wl, g_wl);
    cudaGetSymbolAddress((void**)&ch, g_ch);
    cudaGetSymbolAddress((void**)&cl, g_cl);

    cudaFuncSetAttribute(attn_kernel,
                         cudaFuncAttributeMaxDynamicSharedMemorySize,
                         ATTN_SMEM_BYTES);
    cudaFuncSetAttribute(gemm_tc_kernel,
                         cudaFuncAttributeMaxDynamicSharedMemorySize,
                         GEMM_SMEM);

    const size_t DD = (size_t)DM * DM;
    const int n4x = MTOT * DM / 4;
    const int n4w = DM * DM / 4;

    // splits
    split_kernel<<<(n4x + 255) / 256, 256>>>(x,  xh, xl, n4x);
    split_kernel<<<(n4w + 255) / 256, 256>>>(Wq, wh + 0 * DD, wl + 0 * DD, n4w);
    split_kernel<<<(n4w + 255) / 256, 256>>>(Wk, wh + 1 * DD, wl + 1 * DD, n4w);
    split_kernel<<<(n4w + 255) / 256, 256>>>(Wv, wh + 2 * DD, wl + 2 * DD, n4w);
    split_kernel<<<(n4w + 255) / 256, 256>>>(Wo, wh + 3 * DD, wl + 3 * DD, n4w);

    // Q/K/V projections on tensor cores (HMMA mma.sync)
    dim3 ggrid(DM / 128, MTOT / 128);     // (16, 64)
    gemm_tc_kernel<<<ggrid, 256, GEMM_SMEM>>>(xh, xl, wh + 0 * DD, wl + 0 * DD, qp, 1);
    gemm_tc_kernel<<<ggrid, 256, GEMM_SMEM>>>(xh, xl, wh + 1 * DD, wl + 1 * DD, kp, 1);
    gemm_tc_kernel<<<ggrid, 256, GEMM_SMEM>>>(xh, xl, wh + 2 * DD, wl + 2 * DD, vp, 1);

    // attention (fp32 SIMT)
    dim3 agrid(SL / BQ, BB * HN);         // (32, 64)
    attn_kernel<<<agrid, 256, ATTN_SMEM_BYTES>>>(qp, kp, vp, cp, umk);

    // output projection
    split_kernel<<<(n4x + 255) / 256, 256>>>(cp, ch, cl, n4x);
    gemm_tc_kernel<<<ggrid, 256, GEMM_SMEM>>>(ch, cl, wh + 3 * DD, wl + 3 * DD, out, 0);
}